// round 3
// baseline (speedup 1.0000x reference)
#include <cuda_runtime.h>

// ---------------------------------------------------------------------------
// ContourRec: 2-level contourlet DFB reconstruction (4 subbands).
//
// Stage A (fbrec '2c', 'per'), inputs Y0=[y1;y2], Y1=[y0;y3], 8x64 images of
// 128x128 -> fully fused per-image kernel (whole image + scratch in smem),
// writes x (8x64 images of 128x256).
// Stage B (fbrec '1r', 'qper_col'), x0=x[:, :32], x1=x[:, 32:]:
//   K4: q1 = -1/sqrt2 * (x1 + sefilter_qper(x0, off=5))     (tiled)
//   K5: q0 = sqrt2*x0 + sefilter_qper(q1, off=6)            (tiled)
//   K6: out = qprec_1r(q0, q1)  (gather)
//
// Filter: f = [0.0144, 0.0272, 0.0526, 0.0972, 0.193, 0.63,
//              -0.63, -0.193, -0.0972, -0.0526, -0.0272, -0.0144]
// sefilter2(x, f, ext, shift=(s,s)):
//   out[i,j] = sum_{t,u} f[t] f[u] E(i+t-5-s, j+u-5-s)
//   per:      E(r,c) = x[r mod R, c mod C]
//   qper_col: E(r,c): if r wraps (once), row = r mod R, col = (c mod C) ^ C/2
// qprec_2c(p0,p1) (m=128,n=128 -> 128x256):
//   col=(i+j)%256; even: p0[(i-col/2)%128, col/2]; odd: p1[(i-1-col/2)%128, col>>1]
// qprec_1r(p0,p1) (m=128,n=256 -> 256x256):
//   row=(i+j)%256; even: p0[row/2, (j-row/2)%256]; odd: p1[row>>1, (j-1-(row>>1))%256]
// ---------------------------------------------------------------------------

#define P1 130                      // stage-A smem pitch (floats)
#define INV_SQRT2 0.70710678118654752f
#define SQRT2     1.41421356237309505f

// Scratch (device globals: allocation-free rule)
__device__ float g_x [16777216];    // 8*64*128*256
__device__ float g_q1[ 8388608];    // 8*32*128*256
__device__ float g_q0[ 8388608];

#define DEF_FILT const float FILT[12] = {0.0144f, 0.0272f, 0.0526f, 0.0972f, \
    0.193f, 0.63f, -0.63f, -0.193f, -0.0972f, -0.0526f, -0.0272f, -0.0144f}

// ---------------- Stage A: fully fused per-image kernel --------------------
// smem: A (Y0 -> later p0), B (scratch), C (t1 -> p1). 3 * 128*130*4 = 199,680 B.

__device__ __forceinline__ void hconvA(const float* __restrict__ S,
                                       float* __restrict__ D, int off, int tid)
{
    DEF_FILT;
    const int j  = tid & 127;
    const int i0 = (tid >> 7) * 32;
    #pragma unroll
    for (int ck = 0; ck < 2; ++ck) {
        const int ib = i0 + 16 * ck - off;
        float buf[27];
        #pragma unroll
        for (int k = 0; k < 27; ++k) buf[k] = S[((ib + k) & 127) * P1 + j];
        #pragma unroll
        for (int r = 0; r < 16; ++r) {
            float acc = 0.f;
            #pragma unroll
            for (int t = 0; t < 12; ++t) acc = fmaf(FILT[t], buf[r + t], acc);
            D[(i0 + 16 * ck + r) * P1 + j] = acc;
        }
    }
}

template <bool COMBINE>  // COMBINE: D = sqrt2*D + conv(S); else D = conv(S)
__device__ __forceinline__ void wconvA(const float* __restrict__ S,
                                       float* __restrict__ D, int off, int tid)
{
    DEF_FILT;
    const int i  = tid & 127;
    const int j0 = (tid >> 7) * 32;
    const float* row = S + i * P1;
    #pragma unroll
    for (int ck = 0; ck < 2; ++ck) {
        const int jb = j0 + 16 * ck - off;
        float buf[27];
        #pragma unroll
        for (int k = 0; k < 27; ++k) buf[k] = row[(jb + k) & 127];
        #pragma unroll
        for (int r = 0; r < 16; ++r) {
            float acc = 0.f;
            #pragma unroll
            for (int t = 0; t < 12; ++t) acc = fmaf(FILT[t], buf[r + t], acc);
            const int o = i * P1 + j0 + 16 * ck + r;
            if (COMBINE) D[o] = SQRT2 * D[o] + acc;
            else         D[o] = acc;
        }
    }
}

__global__ __launch_bounds__(512) void stageA_kernel(
    const float* __restrict__ y0, const float* __restrict__ y1,
    const float* __restrict__ y2, const float* __restrict__ y3)
{
    extern __shared__ float sm[];
    float* A = sm;                  // Y0 image, later p0 (in place)
    float* B = sm + 128 * P1;       // scratch
    float* C = sm + 2 * 128 * P1;   // t1 -> p1

    const int img = blockIdx.x;     // b*64 + ch
    const int b = img >> 6, ch = img & 63;
    const float* gY0;
    const float* gY1;
    if (ch < 32) { gY0 = y1 + (b * 32 + ch) * 16384;
                   gY1 = y0 + (b * 32 + ch) * 16384; }
    else         { gY0 = y2 + (b * 32 + ch - 32) * 16384;
                   gY1 = y3 + (b * 32 + ch - 32) * 16384; }

    const int tid = threadIdx.x;

    // load Y0
    for (int idx = tid; idx < 16384; idx += 512)
        A[(idx >> 7) * P1 + (idx & 127)] = gY0[idx];
    __syncthreads();

    hconvA(A, B, 5, tid);           // B = Hconv(Y0)
    __syncthreads();
    wconvA<false>(B, C, 5, tid);    // C = t1 = sefilter(Y0)
    __syncthreads();

    // C = p1 = -1/sqrt2 * (Y1 + t1)
    for (int idx = tid; idx < 16384; idx += 512) {
        const int o = (idx >> 7) * P1 + (idx & 127);
        C[o] = -INV_SQRT2 * (gY1[idx] + C[o]);
    }
    __syncthreads();

    hconvA(C, B, 6, tid);           // B = Hconv(p1), shift (1,1)
    __syncthreads();
    wconvA<true>(B, A, 6, tid);     // A = p0 = sqrt2*Y0 + Wconv(B)
    __syncthreads();

    // qprec '2c': x[i,j]; col=(i+j)%256
    float* gx = g_x + img * 32768;
    for (int idx = tid; idx < 32768; idx += 512) {
        const int i = idx >> 8, j = idx & 255;
        const int col = (i + j) & 255;
        const int h = col >> 1;
        float v;
        if (col & 1) v = C[((i - 1 - h) & 127) * P1 + h];
        else         v = A[((i - h) & 127) * P1 + h];
        gx[idx] = v;
    }
}

// ---------------- Stage B: tiled sefilter (qper_col) -----------------------
// 64x64 output tile, 11-halo: Ein 75x75, tmp 64x75, O reuses Ein (pitch 65).

template <int OFF, bool ISQ0>
__global__ __launch_bounds__(256) void stageB_kernel()
{
    __shared__ float sEin[75 * 75];
    __shared__ float sTmp[64 * 75];

    const int tid  = threadIdx.x;
    const int tj   = blockIdx.x * 64;
    const int ti   = blockIdx.y * 64;
    const int img2 = blockIdx.z;                          // b*32 + c
    const int x0base = ((img2 >> 5) * 64 + (img2 & 31)) * 32768;

    const float* src = ISQ0 ? (g_q1 + img2 * 32768) : (g_x + x0base);
    DEF_FILT;

    // load extended tile (qper_col extension)
    for (int idx = tid; idx < 75 * 75; idx += 256) {
        const int r = idx / 75;
        const int c = idx - r * 75;
        int gr = ti + r - OFF;
        int gc = (tj + c - OFF) & 255;
        if (gr < 0)         { gr += 128; gc ^= 128; }
        else if (gr >= 128) { gr -= 128; gc ^= 128; }
        sEin[idx] = src[gr * 256 + gc];
    }
    __syncthreads();

    // Hconv: tmp[r][c] = sum_t f[t] * Ein[r+t][c], r in [0,64), c in [0,75)
    for (int u = tid; u < 300; u += 256) {
        const int strip = u / 75;
        const int c  = u - strip * 75;
        const int rs = strip * 16;
        float buf[27];
        #pragma unroll
        for (int k = 0; k < 27; ++k) buf[k] = sEin[(rs + k) * 75 + c];
        #pragma unroll
        for (int r = 0; r < 16; ++r) {
            float acc = 0.f;
            #pragma unroll
            for (int t = 0; t < 12; ++t) acc = fmaf(FILT[t], buf[r + t], acc);
            sTmp[(rs + r) * 75 + c] = acc;
        }
    }
    __syncthreads();

    // Wconv: O[r][q] = sum_t f[t] * tmp[r][q+t]  (O reuses sEin, pitch 65)
    {
        const int r  = tid & 63;
        const int cs = (tid >> 6) * 16;
        float buf[27];
        #pragma unroll
        for (int k = 0; k < 27; ++k) buf[k] = sTmp[r * 75 + cs + k];
        #pragma unroll
        for (int q = 0; q < 16; ++q) {
            float acc = 0.f;
            #pragma unroll
            for (int t = 0; t < 12; ++t) acc = fmaf(FILT[t], buf[q + t], acc);
            sEin[r * 65 + cs + q] = acc;
        }
    }
    __syncthreads();

    // combine + coalesced global write
    for (int idx = tid; idx < 4096; idx += 256) {
        const int r  = idx >> 6;
        const int cc = idx & 63;
        const int g  = (ti + r) * 256 + (tj + cc);
        const float v = sEin[r * 65 + cc];
        if (ISQ0)
            g_q0[img2 * 32768 + g] = SQRT2 * g_x[x0base + g] + v;
        else
            g_q1[img2 * 32768 + g] =
                -INV_SQRT2 * (g_x[x0base + 32 * 32768 + g] + v);
    }
}

// ---------------- K6: qprec '1r' gather ------------------------------------

__global__ __launch_bounds__(512) void qprec1r_kernel(float* __restrict__ out)
{
    const int idx  = blockIdx.x * 512 + threadIdx.x;
    const int j    = idx & 255;
    const int i    = (idx >> 8) & 255;
    const int img2 = idx >> 16;
    const int row  = (i + j) & 255;
    const int r    = row >> 1;
    float v;
    if (row & 1) v = g_q1[img2 * 32768 + r * 256 + ((j - 1 - r) & 255)];
    else         v = g_q0[img2 * 32768 + r * 256 + ((j - r) & 255)];
    out[idx] = v;
}

// ---------------------------------------------------------------------------

extern "C" void kernel_launch(void* const* d_in, const int* in_sizes, int n_in,
                              void* d_out, int out_size)
{
    const float* y0 = (const float*)d_in[0];
    const float* y1 = (const float*)d_in[1];
    const float* y2 = (const float*)d_in[2];
    const float* y3 = (const float*)d_in[3];

    static bool once = []() {
        cudaFuncSetAttribute(stageA_kernel,
                             cudaFuncAttributeMaxDynamicSharedMemorySize,
                             3 * 128 * P1 * 4);
        return true;
    }();
    (void)once;

    stageA_kernel<<<512, 512, 3 * 128 * P1 * 4>>>(y0, y1, y2, y3);
    stageB_kernel<5, false><<<dim3(4, 2, 256), 256>>>();   // q1
    stageB_kernel<6, true ><<<dim3(4, 2, 256), 256>>>();   // q0
    qprec1r_kernel<<<32768, 512>>>((float*)d_out);
}

// round 4
// speedup vs baseline: 1.0275x; 1.0275x over previous
#include <cuda_runtime.h>

// ---------------------------------------------------------------------------
// ContourRec: 2-level contourlet DFB reconstruction (4 subbands).
// Stage A (fbrec '2c','per'): fully fused per-image kernel (image in smem).
// Stage B (fbrec '1r','qper_col'): K4 (q1), K5 (q0) tiled sefilters.
// K6: qprec '1r' rewritten as scatter-via-smem with fully coalesced global IO:
//   q0[r,c] -> out[(r-c)&255, (r+c)&255],  q1[r,c] -> out[(r-c)&255, (r+c+1)&255]
//   For fixed out-row u and r-chunk [r0,r0+16): contiguous 32-col run at
//   column (2*r0-u)&255, alternating q0/q1.
// ---------------------------------------------------------------------------

#define P1 130                      // stage-A smem pitch (floats)
#define INV_SQRT2 0.70710678118654752f
#define SQRT2     1.41421356237309505f

// Scratch (device globals: allocation-free rule)
__device__ float g_x [16777216];    // 8*64*128*256
__device__ float g_q1[ 8388608];    // 8*32*128*256
__device__ float g_q0[ 8388608];

#define DEF_FILT const float FILT[12] = {0.0144f, 0.0272f, 0.0526f, 0.0972f, \
    0.193f, 0.63f, -0.63f, -0.193f, -0.0972f, -0.0526f, -0.0272f, -0.0144f}

// ---------------- Stage A: fully fused per-image kernel (1024 thr) ---------
// smem: A (Y0 -> later p0), B (scratch), C (t1 -> p1). 3 * 128*130*4 = 199,680 B.

__device__ __forceinline__ void hconvA(const float* __restrict__ S,
                                       float* __restrict__ D, int off, int tid)
{
    DEF_FILT;
    const int j  = tid & 127;
    const int i0 = (tid >> 7) * 16;          // 8 groups x 16 rows
    const int ib = i0 - off;
    float buf[27];
    #pragma unroll
    for (int k = 0; k < 27; ++k) buf[k] = S[((ib + k) & 127) * P1 + j];
    #pragma unroll
    for (int r = 0; r < 16; ++r) {
        float acc = 0.f;
        #pragma unroll
        for (int t = 0; t < 12; ++t) acc = fmaf(FILT[t], buf[r + t], acc);
        D[(i0 + r) * P1 + j] = acc;
    }
}

template <bool COMBINE>  // COMBINE: D = sqrt2*D + conv(S); else D = conv(S)
__device__ __forceinline__ void wconvA(const float* __restrict__ S,
                                       float* __restrict__ D, int off, int tid)
{
    DEF_FILT;
    const int i  = tid & 127;
    const int j0 = (tid >> 7) * 16;
    const float* row = S + i * P1;
    const int jb = j0 - off;
    float buf[27];
    #pragma unroll
    for (int k = 0; k < 27; ++k) buf[k] = row[(jb + k) & 127];
    #pragma unroll
    for (int r = 0; r < 16; ++r) {
        float acc = 0.f;
        #pragma unroll
        for (int t = 0; t < 12; ++t) acc = fmaf(FILT[t], buf[r + t], acc);
        const int o = i * P1 + j0 + r;
        if (COMBINE) D[o] = SQRT2 * D[o] + acc;
        else         D[o] = acc;
    }
}

__global__ __launch_bounds__(1024) void stageA_kernel(
    const float* __restrict__ y0, const float* __restrict__ y1,
    const float* __restrict__ y2, const float* __restrict__ y3)
{
    extern __shared__ float sm[];
    float* A = sm;                  // Y0 image, later p0 (in place)
    float* B = sm + 128 * P1;       // scratch
    float* C = sm + 2 * 128 * P1;   // t1 -> p1

    const int img = blockIdx.x;     // b*64 + ch
    const int b = img >> 6, ch = img & 63;
    const float* gY0;
    const float* gY1;
    if (ch < 32) { gY0 = y1 + (b * 32 + ch) * 16384;
                   gY1 = y0 + (b * 32 + ch) * 16384; }
    else         { gY0 = y2 + (b * 32 + ch - 32) * 16384;
                   gY1 = y3 + (b * 32 + ch - 32) * 16384; }

    const int tid = threadIdx.x;

    // load Y0
    for (int idx = tid; idx < 16384; idx += 1024)
        A[(idx >> 7) * P1 + (idx & 127)] = gY0[idx];
    __syncthreads();

    hconvA(A, B, 5, tid);           // B = Hconv(Y0)
    __syncthreads();
    wconvA<false>(B, C, 5, tid);    // C = t1 = sefilter(Y0)
    __syncthreads();

    // C = p1 = -1/sqrt2 * (Y1 + t1)
    for (int idx = tid; idx < 16384; idx += 1024) {
        const int o = (idx >> 7) * P1 + (idx & 127);
        C[o] = -INV_SQRT2 * (gY1[idx] + C[o]);
    }
    __syncthreads();

    hconvA(C, B, 6, tid);           // B = Hconv(p1), shift (1,1)
    __syncthreads();
    wconvA<true>(B, A, 6, tid);     // A = p0 = sqrt2*Y0 + Wconv(B)
    __syncthreads();

    // qprec '2c': x[i,j]; col=(i+j)%256
    float* gx = g_x + img * 32768;
    for (int idx = tid; idx < 32768; idx += 1024) {
        const int i = idx >> 8, j = idx & 255;
        const int col = (i + j) & 255;
        const int h = col >> 1;
        float v;
        if (col & 1) v = C[((i - 1 - h) & 127) * P1 + h];
        else         v = A[((i - h) & 127) * P1 + h];
        gx[idx] = v;
    }
}

// ---------------- Stage B: tiled sefilter (qper_col) -----------------------
// 64x64 output tile, 11-halo: Ein 75x75, tmp 64x75, O reuses Ein (pitch 65).

template <int OFF, bool ISQ0>
__global__ __launch_bounds__(256) void stageB_kernel()
{
    __shared__ float sEin[75 * 75];
    __shared__ float sTmp[64 * 75];

    const int tid  = threadIdx.x;
    const int tj   = blockIdx.x * 64;
    const int ti   = blockIdx.y * 64;
    const int img2 = blockIdx.z;                          // b*32 + c
    const int x0base = ((img2 >> 5) * 64 + (img2 & 31)) * 32768;

    const float* src = ISQ0 ? (g_q1 + img2 * 32768) : (g_x + x0base);
    DEF_FILT;

    // load extended tile (qper_col extension)
    for (int idx = tid; idx < 75 * 75; idx += 256) {
        const int r = idx / 75;
        const int c = idx - r * 75;
        int gr = ti + r - OFF;
        int gc = (tj + c - OFF) & 255;
        if (gr < 0)         { gr += 128; gc ^= 128; }
        else if (gr >= 128) { gr -= 128; gc ^= 128; }
        sEin[idx] = src[gr * 256 + gc];
    }
    __syncthreads();

    // Hconv: tmp[r][c] = sum_t f[t] * Ein[r+t][c], r in [0,64), c in [0,75)
    for (int u = tid; u < 300; u += 256) {
        const int strip = u / 75;
        const int c  = u - strip * 75;
        const int rs = strip * 16;
        float buf[27];
        #pragma unroll
        for (int k = 0; k < 27; ++k) buf[k] = sEin[(rs + k) * 75 + c];
        #pragma unroll
        for (int r = 0; r < 16; ++r) {
            float acc = 0.f;
            #pragma unroll
            for (int t = 0; t < 12; ++t) acc = fmaf(FILT[t], buf[r + t], acc);
            sTmp[(rs + r) * 75 + c] = acc;
        }
    }
    __syncthreads();

    // Wconv: O[r][q] = sum_t f[t] * tmp[r][q+t]  (O reuses sEin, pitch 65)
    {
        const int r  = tid & 63;
        const int cs = (tid >> 6) * 16;
        float buf[27];
        #pragma unroll
        for (int k = 0; k < 27; ++k) buf[k] = sTmp[r * 75 + cs + k];
        #pragma unroll
        for (int q = 0; q < 16; ++q) {
            float acc = 0.f;
            #pragma unroll
            for (int t = 0; t < 12; ++t) acc = fmaf(FILT[t], buf[q + t], acc);
            sEin[r * 65 + cs + q] = acc;
        }
    }
    __syncthreads();

    // combine + coalesced global write
    for (int idx = tid; idx < 4096; idx += 256) {
        const int r  = idx >> 6;
        const int cc = idx & 63;
        const int g  = (ti + r) * 256 + (tj + cc);
        const float v = sEin[r * 65 + cc];
        if (ISQ0)
            g_q0[img2 * 32768 + g] = SQRT2 * g_x[x0base + g] + v;
        else
            g_q1[img2 * 32768 + g] =
                -INV_SQRT2 * (g_x[x0base + 32 * 32768 + g] + v);
    }
}

// ---------------- K6: qprec '1r' via smem staging --------------------------
// Block handles one 16-row chunk [r0, r0+16) of (q0,q1) for one image.
// Loads are coalesced; q0/q1 interleaved in smem (float2 layout as floats).
// Each warp writes contiguous 32-float runs of one output row.
// out[u, (2*r0-u+w)&255] = w even ? q0[r0+w/2, (r0+w/2-u)&255]
//                                 : q1[r0+(w-1)/2, (r0+(w-1)/2-u)&255]

__global__ __launch_bounds__(512) void qprec1r_kernel(float* __restrict__ out)
{
    __shared__ float sm2[16 * 512];           // [k][col*2 + (0:q0,1:q1)]

    const int tid  = threadIdx.x;
    const int r0   = (blockIdx.x & 7) * 16;   // 8 chunks of 16 rows
    const int img2 = blockIdx.x >> 3;

    const float* q0 = g_q0 + img2 * 32768 + r0 * 256;
    const float* q1 = g_q1 + img2 * 32768 + r0 * 256;

    for (int idx = tid; idx < 4096; idx += 512) {
        sm2[2 * idx]     = q0[idx];
        sm2[2 * idx + 1] = q1[idx];
    }
    __syncthreads();

    float* o = out + img2 * 65536;
    const int w   = tid & 31;                 // position in 32-col run
    const int u0  = tid >> 5;                 // 0..15
    const int k   = w >> 1;                   // source row within chunk
    const int lsb = w & 1;
    const int cb  = r0 + k;                   // col = (cb - u) & 255

    #pragma unroll 4
    for (int uu = 0; uu < 16; ++uu) {
        const int u = uu * 16 + u0;
        const int j = (2 * r0 - u + w) & 255;
        o[u * 256 + j] = sm2[k * 512 + 2 * ((cb - u) & 255) + lsb];
    }
}

// ---------------------------------------------------------------------------

extern "C" void kernel_launch(void* const* d_in, const int* in_sizes, int n_in,
                              void* d_out, int out_size)
{
    const float* y0 = (const float*)d_in[0];
    const float* y1 = (const float*)d_in[1];
    const float* y2 = (const float*)d_in[2];
    const float* y3 = (const float*)d_in[3];

    static bool once = []() {
        cudaFuncSetAttribute(stageA_kernel,
                             cudaFuncAttributeMaxDynamicSharedMemorySize,
                             3 * 128 * P1 * 4);
        return true;
    }();
    (void)once;

    stageA_kernel<<<512, 1024, 3 * 128 * P1 * 4>>>(y0, y1, y2, y3);
    stageB_kernel<5, false><<<dim3(4, 2, 256), 256>>>();   // q1
    stageB_kernel<6, true ><<<dim3(4, 2, 256), 256>>>();   // q0
    qprec1r_kernel<<<2048, 512>>>((float*)d_out);
}

// round 5
// speedup vs baseline: 1.1071x; 1.0775x over previous
#include <cuda_runtime.h>
#include <cstdint>

// ---------------------------------------------------------------------------
// ContourRec: 2-level contourlet DFB reconstruction (4 subbands).
// Stage A (fbrec '2c','per'): fully fused per-image kernel (image in smem),
//   512 threads (R3 config — 1024 caused register spills).
// Stage B (fbrec '1r','qper_col') + qprec '1r': ONE fused kernel, 2-CTA
//   cluster per 128x256 image. Each CTA owns 64 rows of q1/q0 in smem.
//   Phase 1: q1 = -1/sqrt2 (x1 + sefilter_qper(x0, off=5))   [x0 from gmem]
//   Phase 2: q0 = sqrt2*x0 + sefilter_qper(q1, off=6)        [q1 halo: DSMEM]
//   Phase 3: out row (u+j)&255 in [128h,128h+128) <=> r in [64h,64h+64)
//            -> each CTA scatters only from ITS OWN q0/q1 rows, bank-free.
// ---------------------------------------------------------------------------

#define P1 130
#define INV_SQRT2 0.70710678118654752f
#define SQRT2     1.41421356237309505f

__device__ float g_x[16777216];     // 8*64*128*256 (stage-A output)

#define DEF_FILT const float FILT[12] = {0.0144f, 0.0272f, 0.0526f, 0.0972f, \
    0.193f, 0.63f, -0.63f, -0.193f, -0.0972f, -0.0526f, -0.0272f, -0.0144f}

// ---------------- Stage A: fully fused per-image kernel (512 thr) ----------

__device__ __forceinline__ void hconvA(const float* __restrict__ S,
                                       float* __restrict__ D, int off, int tid)
{
    DEF_FILT;
    const int j  = tid & 127;
    const int i0 = (tid >> 7) * 32;
    #pragma unroll
    for (int ck = 0; ck < 2; ++ck) {
        const int ib = i0 + 16 * ck - off;
        float buf[27];
        #pragma unroll
        for (int k = 0; k < 27; ++k) buf[k] = S[((ib + k) & 127) * P1 + j];
        #pragma unroll
        for (int r = 0; r < 16; ++r) {
            float acc = 0.f;
            #pragma unroll
            for (int t = 0; t < 12; ++t) acc = fmaf(FILT[t], buf[r + t], acc);
            D[(i0 + 16 * ck + r) * P1 + j] = acc;
        }
    }
}

template <bool COMBINE>
__device__ __forceinline__ void wconvA(const float* __restrict__ S,
                                       float* __restrict__ D, int off, int tid)
{
    DEF_FILT;
    const int i  = tid & 127;
    const int j0 = (tid >> 7) * 32;
    const float* row = S + i * P1;
    #pragma unroll
    for (int ck = 0; ck < 2; ++ck) {
        const int jb = j0 + 16 * ck - off;
        float buf[27];
        #pragma unroll
        for (int k = 0; k < 27; ++k) buf[k] = row[(jb + k) & 127];
        #pragma unroll
        for (int r = 0; r < 16; ++r) {
            float acc = 0.f;
            #pragma unroll
            for (int t = 0; t < 12; ++t) acc = fmaf(FILT[t], buf[r + t], acc);
            const int o = i * P1 + j0 + 16 * ck + r;
            if (COMBINE) D[o] = SQRT2 * D[o] + acc;
            else         D[o] = acc;
        }
    }
}

__global__ __launch_bounds__(512) void stageA_kernel(
    const float* __restrict__ y0, const float* __restrict__ y1,
    const float* __restrict__ y2, const float* __restrict__ y3)
{
    extern __shared__ float sm[];
    float* A = sm;
    float* B = sm + 128 * P1;
    float* C = sm + 2 * 128 * P1;

    const int img = blockIdx.x;
    const int b = img >> 6, ch = img & 63;
    const float* gY0;
    const float* gY1;
    if (ch < 32) { gY0 = y1 + (b * 32 + ch) * 16384;
                   gY1 = y0 + (b * 32 + ch) * 16384; }
    else         { gY0 = y2 + (b * 32 + ch - 32) * 16384;
                   gY1 = y3 + (b * 32 + ch - 32) * 16384; }

    const int tid = threadIdx.x;

    for (int idx = tid; idx < 16384; idx += 512)
        A[(idx >> 7) * P1 + (idx & 127)] = gY0[idx];
    __syncthreads();

    hconvA(A, B, 5, tid);
    __syncthreads();
    wconvA<false>(B, C, 5, tid);
    __syncthreads();

    for (int idx = tid; idx < 16384; idx += 512) {
        const int o = (idx >> 7) * P1 + (idx & 127);
        C[o] = -INV_SQRT2 * (gY1[idx] + C[o]);
    }
    __syncthreads();

    hconvA(C, B, 6, tid);
    __syncthreads();
    wconvA<true>(B, A, 6, tid);
    __syncthreads();

    float* gx = g_x + img * 32768;
    for (int idx = tid; idx < 32768; idx += 512) {
        const int i = idx >> 8, j = idx & 255;
        const int col = (i + j) & 255;
        const int h = col >> 1;
        float v;
        if (col & 1) v = C[((i - 1 - h) & 127) * P1 + h];
        else         v = A[((i - h) & 127) * P1 + h];
        gx[idx] = v;
    }
}

// ---------------- Fused Stage B + qprec (2-CTA cluster per image) ----------

#define QP  264                     // q pitch: (QP+1)%32=9 (odd) -> bank-free
#define EP  267
#define TP  267
#define Q0OFF 0
#define Q1OFF 16912                 // 64*264 + 16 -> Q1 banks = complement set
#define EOFF  33808
#define TOFF  41017
#define SMB_BYTES (45289 * 4)       // 181,156 B

__device__ __forceinline__ uint32_t smem_u32(const void* p) {
    uint32_t a;
    asm("{ .reg .u64 t; cvta.to.shared.u64 t, %1; cvt.u32.u64 %0, t; }"
        : "=r"(a) : "l"(p));
    return a;
}
__device__ __forceinline__ uint32_t mapa_rank(uint32_t addr, uint32_t rank) {
    uint32_t r;
    asm("mapa.shared::cluster.u32 %0, %1, %2;" : "=r"(r) : "r"(addr), "r"(rank));
    return r;
}
__device__ __forceinline__ float ld_dsm(uint32_t addr) {
    float v;
    asm volatile("ld.shared::cluster.f32 %0, [%1];" : "=f"(v) : "r"(addr));
    return v;
}
#define CLUSTER_SYNC() do { \
    asm volatile("barrier.cluster.arrive.aligned;" ::: "memory"); \
    asm volatile("barrier.cluster.wait.aligned;"  ::: "memory"); } while (0)

__global__ __launch_bounds__(512) __cluster_dims__(2, 1, 1)
void stageB_fused(float* __restrict__ out)
{
    extern __shared__ float smB[];
    float* Q0 = smB + Q0OFF;
    float* Q1 = smB + Q1OFF;
    float* E  = smB + EOFF;
    float* T  = smB + TOFF;

    const int tid  = threadIdx.x;
    const int lane = tid & 31;
    const int wrp  = tid >> 5;
    uint32_t hr;
    asm("mov.u32 %0, %%cluster_ctarank;" : "=r"(hr));
    const int h    = (int)hr;
    const int img2 = blockIdx.x >> 1;
    const int x0base = ((img2 >> 5) * 64 + (img2 & 31)) * 32768;
    const float* x0g = g_x + x0base;
    const float* x1g = x0g + 32 * 32768;

    const uint32_t q1PeerBase = mapa_rank(smem_u32(Q1), hr ^ 1u);

    DEF_FILT;

    // ---- phase 1: Q1[s..s+16) = -1/sqrt2 (x1 + sefilter(x0, off=5)) ------
    for (int s = 0; s < 64; s += 16) {
        const int rowbase = 64 * h + s - 5;
        for (int idx = tid; idx < 7209; idx += 512) {        // 27 x 267
            const int k = idx / 267;
            const int c = idx - k * 267;
            int gr = rowbase + k;
            int cm = (c - 5) & 255;
            if (gr < 0)         { gr += 128; cm ^= 128; }
            else if (gr >= 128) { gr -= 128; cm ^= 128; }
            E[k * EP + c] = x0g[gr * 256 + cm];
        }
        __syncthreads();

        for (int u = tid; u < 534; u += 512) {               // Hconv
            const int half = (u >= 267);
            const int c  = u - (half ? 267 : 0);
            const int rs = half ? 8 : 0;
            float buf[19];
            #pragma unroll
            for (int k = 0; k < 19; ++k) buf[k] = E[(rs + k) * EP + c];
            #pragma unroll
            for (int r = 0; r < 8; ++r) {
                float acc = 0.f;
                #pragma unroll
                for (int t = 0; t < 12; ++t) acc = fmaf(FILT[t], buf[r + t], acc);
                T[(rs + r) * TP + c] = acc;
            }
        }
        __syncthreads();

        {                                                    // Wconv + combine
            const int i = wrp;                               // 16 warps = rows
            float acc[8];
            #pragma unroll
            for (int m = 0; m < 8; ++m) acc[m] = 0.f;
            #pragma unroll
            for (int u = 0; u < 12; ++u) {
                const float fv = FILT[u];
                const float* tr = T + i * TP + lane + u;
                #pragma unroll
                for (int m = 0; m < 8; ++m)
                    acc[m] = fmaf(fv, tr[32 * m], acc[m]);
            }
            const int gi = 64 * h + s + i;
            #pragma unroll
            for (int m = 0; m < 8; ++m) {
                const int j = lane + 32 * m;
                Q1[(s + i) * QP + j] =
                    -INV_SQRT2 * (x1g[gi * 256 + j] + acc[m]);
            }
        }
        __syncthreads();
    }

    CLUSTER_SYNC();     // peer Q1 complete before halo reads

    // ---- phase 2: Q0[s..s+16) = sqrt2*x0 + sefilter(Q1, off=6) -----------
    for (int s = 0; s < 64; s += 16) {
        const int rowbase = 64 * h + s - 6;
        for (int idx = tid; idx < 7209; idx += 512) {
            const int k = idx / 267;
            const int c = idx - k * 267;
            int gr = rowbase + k;
            int cm = (c - 6) & 255;
            if (gr < 0)         { gr += 128; cm ^= 128; }
            else if (gr >= 128) { gr -= 128; cm ^= 128; }
            const int owner = gr >> 6;
            const int lr    = gr & 63;
            float v;
            if (owner == h) v = Q1[lr * QP + cm];
            else            v = ld_dsm(q1PeerBase + (uint32_t)(lr * QP + cm) * 4u);
            E[k * EP + c] = v;
        }
        __syncthreads();

        for (int u = tid; u < 534; u += 512) {               // Hconv
            const int half = (u >= 267);
            const int c  = u - (half ? 267 : 0);
            const int rs = half ? 8 : 0;
            float buf[19];
            #pragma unroll
            for (int k = 0; k < 19; ++k) buf[k] = E[(rs + k) * EP + c];
            #pragma unroll
            for (int r = 0; r < 8; ++r) {
                float acc = 0.f;
                #pragma unroll
                for (int t = 0; t < 12; ++t) acc = fmaf(FILT[t], buf[r + t], acc);
                T[(rs + r) * TP + c] = acc;
            }
        }
        __syncthreads();

        {                                                    // Wconv + combine
            const int i = wrp;
            float acc[8];
            #pragma unroll
            for (int m = 0; m < 8; ++m) acc[m] = 0.f;
            #pragma unroll
            for (int u = 0; u < 12; ++u) {
                const float fv = FILT[u];
                const float* tr = T + i * TP + lane + u;
                #pragma unroll
                for (int m = 0; m < 8; ++m)
                    acc[m] = fmaf(fv, tr[32 * m], acc[m]);
            }
            const int gi = 64 * h + s + i;
            #pragma unroll
            for (int m = 0; m < 8; ++m) {
                const int j = lane + 32 * m;
                Q0[(s + i) * QP + j] =
                    SQRT2 * x0g[gi * 256 + j] + acc[m];
            }
        }
        __syncthreads();
    }

    // ---- phase 3: qprec '1r' scatter — local rows only, bank-free --------
    // out[u,j]: row=(u+j)&255; even: q0[row/2,(j-row/2)&255];
    //                          odd : q1[row>>1,(j-1-(row>>1))&255]
    {
        float* og = out + img2 * 65536;
        const int base128 = 128 * h;
        #pragma unroll
        for (int p = 0; p < 4; ++p) {
            const int row = base128 + 32 * p + lane;   // in [128h,128h+128)
            const int r   = row >> 1;
            const int lr  = (32 * p + lane) >> 1;
            const float* src = (lane & 1) ? (Q1 + lr * QP) : (Q0 + lr * QP);
            const int coff = (lane & 1) ? (-1 - r) : (-r);
            for (int ui = 0; ui < 16; ++ui) {
                const int u = (wrp << 4) + ui;
                const int j = (base128 - u + 32 * p + lane) & 255;
                og[u * 256 + j] = src[(j + coff) & 255];
            }
        }
    }

    CLUSTER_SYNC();     // keep smem alive while peer may still read (safety)
}

// ---------------------------------------------------------------------------

extern "C" void kernel_launch(void* const* d_in, const int* in_sizes, int n_in,
                              void* d_out, int out_size)
{
    const float* y0 = (const float*)d_in[0];
    const float* y1 = (const float*)d_in[1];
    const float* y2 = (const float*)d_in[2];
    const float* y3 = (const float*)d_in[3];

    static bool once = []() {
        cudaFuncSetAttribute(stageA_kernel,
                             cudaFuncAttributeMaxDynamicSharedMemorySize,
                             3 * 128 * P1 * 4);
        cudaFuncSetAttribute(stageB_fused,
                             cudaFuncAttributeMaxDynamicSharedMemorySize,
                             SMB_BYTES);
        return true;
    }();
    (void)once;

    stageA_kernel<<<512, 512, 3 * 128 * P1 * 4>>>(y0, y1, y2, y3);
    stageB_fused<<<512, 512, SMB_BYTES>>>((float*)d_out);
}

// round 6
// speedup vs baseline: 1.2463x; 1.1257x over previous
#include <cuda_runtime.h>
#include <cstdint>

// ---------------------------------------------------------------------------
// ContourRec: 2-level contourlet DFB reconstruction (4 subbands).
// Stage A (fbrec '2c','per'): fully fused per-image kernel (image in smem).
// Stage B (fbrec '1r','qper_col') + qprec '1r': ONE fused kernel, 2-CTA
//   cluster per 128x256 image, 1024 threads (32 warps), 32-row strips.
// ---------------------------------------------------------------------------

#define P1 130
#define INV_SQRT2 0.70710678118654752f
#define SQRT2     1.41421356237309505f

__device__ float g_x[16777216];     // 8*64*128*256 (stage-A output)

#define DEF_FILT const float FILT[12] = {0.0144f, 0.0272f, 0.0526f, 0.0972f, \
    0.193f, 0.63f, -0.63f, -0.193f, -0.0972f, -0.0526f, -0.0272f, -0.0144f}

// ---------------- Stage A: fully fused per-image kernel (512 thr) ----------

__device__ __forceinline__ void hconvA(const float* __restrict__ S,
                                       float* __restrict__ D, int off, int tid)
{
    DEF_FILT;
    const int j  = tid & 127;
    const int i0 = (tid >> 7) * 32;
    #pragma unroll
    for (int ck = 0; ck < 2; ++ck) {
        const int ib = i0 + 16 * ck - off;
        float buf[27];
        #pragma unroll
        for (int k = 0; k < 27; ++k) buf[k] = S[((ib + k) & 127) * P1 + j];
        #pragma unroll
        for (int r = 0; r < 16; ++r) {
            float acc = 0.f;
            #pragma unroll
            for (int t = 0; t < 12; ++t) acc = fmaf(FILT[t], buf[r + t], acc);
            D[(i0 + 16 * ck + r) * P1 + j] = acc;
        }
    }
}

template <bool COMBINE>
__device__ __forceinline__ void wconvA(const float* __restrict__ S,
                                       float* __restrict__ D, int off, int tid)
{
    DEF_FILT;
    const int i  = tid & 127;
    const int j0 = (tid >> 7) * 32;
    const float* row = S + i * P1;
    #pragma unroll
    for (int ck = 0; ck < 2; ++ck) {
        const int jb = j0 + 16 * ck - off;
        float buf[27];
        #pragma unroll
        for (int k = 0; k < 27; ++k) buf[k] = row[(jb + k) & 127];
        #pragma unroll
        for (int r = 0; r < 16; ++r) {
            float acc = 0.f;
            #pragma unroll
            for (int t = 0; t < 12; ++t) acc = fmaf(FILT[t], buf[r + t], acc);
            const int o = i * P1 + j0 + 16 * ck + r;
            if (COMBINE) D[o] = SQRT2 * D[o] + acc;
            else         D[o] = acc;
        }
    }
}

__global__ __launch_bounds__(512) void stageA_kernel(
    const float* __restrict__ y0, const float* __restrict__ y1,
    const float* __restrict__ y2, const float* __restrict__ y3)
{
    extern __shared__ float sm[];
    float* A = sm;
    float* B = sm + 128 * P1;
    float* C = sm + 2 * 128 * P1;

    const int img = blockIdx.x;
    const int b = img >> 6, ch = img & 63;
    const float* gY0;
    const float* gY1;
    if (ch < 32) { gY0 = y1 + (b * 32 + ch) * 16384;
                   gY1 = y0 + (b * 32 + ch) * 16384; }
    else         { gY0 = y2 + (b * 32 + ch - 32) * 16384;
                   gY1 = y3 + (b * 32 + ch - 32) * 16384; }

    const int tid = threadIdx.x;

    for (int idx = tid; idx < 16384; idx += 512)
        A[(idx >> 7) * P1 + (idx & 127)] = gY0[idx];
    __syncthreads();

    hconvA(A, B, 5, tid);
    __syncthreads();
    wconvA<false>(B, C, 5, tid);
    __syncthreads();

    for (int idx = tid; idx < 16384; idx += 512) {
        const int o = (idx >> 7) * P1 + (idx & 127);
        C[o] = -INV_SQRT2 * (gY1[idx] + C[o]);
    }
    __syncthreads();

    hconvA(C, B, 6, tid);
    __syncthreads();
    wconvA<true>(B, A, 6, tid);
    __syncthreads();

    float* gx = g_x + img * 32768;
    for (int idx = tid; idx < 32768; idx += 512) {
        const int i = idx >> 8, j = idx & 255;
        const int col = (i + j) & 255;
        const int h = col >> 1;
        float v;
        if (col & 1) v = C[((i - 1 - h) & 127) * P1 + h];
        else         v = A[((i - h) & 127) * P1 + h];
        gx[idx] = v;
    }
}

// ---------------- Fused Stage B + qprec (2-CTA cluster, 1024 thr) ----------

#define QP  264                     // q pitch: bank-free phase-3 reads
#define EP  267
#define TP  267
#define Q0OFF 0
#define Q1OFF 16912                 // 64*264 + 16 -> Q1 banks complement Q0's
#define EOFF  33808                 // E: 43 x 267
#define TOFF  45289                 // T: 32 x 267
#define SMB_FLOATS (45289 + 32 * 267)
#define SMB_BYTES (SMB_FLOATS * 4)  // 215,332 B

__device__ __forceinline__ uint32_t smem_u32(const void* p) {
    uint32_t a;
    asm("{ .reg .u64 t; cvta.to.shared.u64 t, %1; cvt.u32.u64 %0, t; }"
        : "=r"(a) : "l"(p));
    return a;
}
__device__ __forceinline__ uint32_t mapa_rank(uint32_t addr, uint32_t rank) {
    uint32_t r;
    asm("mapa.shared::cluster.u32 %0, %1, %2;" : "=r"(r) : "r"(addr), "r"(rank));
    return r;
}
__device__ __forceinline__ float ld_dsm(uint32_t addr) {
    float v;
    asm volatile("ld.shared::cluster.f32 %0, [%1];" : "=f"(v) : "r"(addr));
    return v;
}
#define CLUSTER_SYNC() do { \
    asm volatile("barrier.cluster.arrive.aligned;" ::: "memory"); \
    asm volatile("barrier.cluster.wait.aligned;"  ::: "memory"); } while (0)

__global__ __launch_bounds__(1024) __cluster_dims__(2, 1, 1)
void stageB_fused(float* __restrict__ out)
{
    extern __shared__ float smB[];
    float* Q0 = smB + Q0OFF;
    float* Q1 = smB + Q1OFF;
    float* E  = smB + EOFF;
    float* T  = smB + TOFF;

    const int tid  = threadIdx.x;
    const int lane = tid & 31;
    const int wrp  = tid >> 5;                // 0..31
    uint32_t hr;
    asm("mov.u32 %0, %%cluster_ctarank;" : "=r"(hr));
    const int h    = (int)hr;
    const int img2 = blockIdx.x >> 1;
    const int x0base = ((img2 >> 5) * 64 + (img2 & 31)) * 32768;
    const float* x0g = g_x + x0base;
    const float* x1g = x0g + 32 * 32768;

    const uint32_t q1PeerBase = mapa_rank(smem_u32(Q1), hr ^ 1u);

    DEF_FILT;

    // ---- phase 1: Q1 = -1/sqrt2 (x1 + sefilter(x0, off=5)); 32-row strips -
    #pragma unroll
    for (int s = 0; s < 64; s += 32) {
        const int rowbase = 64 * h + s - 5;
        // E load: warp-per-row, wrap computed once per row (warp-uniform)
        for (int k = wrp; k < 43; k += 32) {
            int gr = rowbase + k;
            int flip = 0;
            if (gr < 0)         { gr += 128; flip = 128; }
            else if (gr >= 128) { gr -= 128; flip = 128; }
            const float* srow = x0g + gr * 256;
            float* erow = E + k * EP;
            for (int c = lane; c < 267; c += 32)
                erow[c] = srow[((c - 5) & 255) ^ flip];
        }
        __syncthreads();

        // Hconv: units of 8 T-rows x 1 column; 4*267 = 1068 units
        for (int u = tid; u < 1068; u += 1024) {
            const int q  = u >> 8;            // not exact; use div-free split:
            (void)q;
            const int quarter = u / 267;
            const int c  = u - quarter * 267;
            const int rs = quarter * 8;
            float buf[19];
            #pragma unroll
            for (int k = 0; k < 19; ++k) buf[k] = E[(rs + k) * EP + c];
            #pragma unroll
            for (int r = 0; r < 8; ++r) {
                float acc = 0.f;
                #pragma unroll
                for (int t = 0; t < 12; ++t) acc = fmaf(FILT[t], buf[r + t], acc);
                T[(rs + r) * TP + c] = acc;
            }
        }
        __syncthreads();

        // Wconv + combine: warp-per-row (32 warps = 32 rows)
        {
            const int i = wrp;
            float acc[8];
            #pragma unroll
            for (int m = 0; m < 8; ++m) acc[m] = 0.f;
            #pragma unroll
            for (int u = 0; u < 12; ++u) {
                const float fv = FILT[u];
                const float* tr = T + i * TP + lane + u;
                #pragma unroll
                for (int m = 0; m < 8; ++m)
                    acc[m] = fmaf(fv, tr[32 * m], acc[m]);
            }
            const int gi = 64 * h + s + i;
            #pragma unroll
            for (int m = 0; m < 8; ++m) {
                const int j = lane + 32 * m;
                Q1[(s + i) * QP + j] =
                    -INV_SQRT2 * (x1g[gi * 256 + j] + acc[m]);
            }
        }
        __syncthreads();
    }

    CLUSTER_SYNC();     // peer Q1 complete before halo reads

    // ---- phase 2: Q0 = sqrt2*x0 + sefilter(Q1, off=6) --------------------
    #pragma unroll
    for (int s = 0; s < 64; s += 32) {
        const int rowbase = 64 * h + s - 6;
        for (int k = wrp; k < 43; k += 32) {
            int gr = rowbase + k;
            int flip = 0;
            if (gr < 0)         { gr += 128; flip = 128; }
            else if (gr >= 128) { gr -= 128; flip = 128; }
            const int owner = gr >> 6;        // warp-uniform
            const int lr    = gr & 63;
            float* erow = E + k * EP;
            if (owner == h) {
                const float* qrow = Q1 + lr * QP;
                for (int c = lane; c < 267; c += 32)
                    erow[c] = qrow[((c - 6) & 255) ^ flip];
            } else {
                const uint32_t pb = q1PeerBase + (uint32_t)(lr * QP) * 4u;
                for (int c = lane; c < 267; c += 32)
                    erow[c] = ld_dsm(pb + (uint32_t)(((c - 6) & 255) ^ flip) * 4u);
            }
        }
        __syncthreads();

        for (int u = tid; u < 1068; u += 1024) {
            const int quarter = u / 267;
            const int c  = u - quarter * 267;
            const int rs = quarter * 8;
            float buf[19];
            #pragma unroll
            for (int k = 0; k < 19; ++k) buf[k] = E[(rs + k) * EP + c];
            #pragma unroll
            for (int r = 0; r < 8; ++r) {
                float acc = 0.f;
                #pragma unroll
                for (int t = 0; t < 12; ++t) acc = fmaf(FILT[t], buf[r + t], acc);
                T[(rs + r) * TP + c] = acc;
            }
        }
        __syncthreads();

        {
            const int i = wrp;
            float acc[8];
            #pragma unroll
            for (int m = 0; m < 8; ++m) acc[m] = 0.f;
            #pragma unroll
            for (int u = 0; u < 12; ++u) {
                const float fv = FILT[u];
                const float* tr = T + i * TP + lane + u;
                #pragma unroll
                for (int m = 0; m < 8; ++m)
                    acc[m] = fmaf(fv, tr[32 * m], acc[m]);
            }
            const int gi = 64 * h + s + i;
            #pragma unroll
            for (int m = 0; m < 8; ++m) {
                const int j = lane + 32 * m;
                Q0[(s + i) * QP + j] =
                    SQRT2 * x0g[gi * 256 + j] + acc[m];
            }
        }
        __syncthreads();
    }

    // ---- phase 3: qprec '1r' scatter — local rows only, bank-free --------
    {
        float* og = out + img2 * 65536;
        const int base128 = 128 * h;
        #pragma unroll
        for (int p = 0; p < 4; ++p) {
            const int row = base128 + 32 * p + lane;
            const int r   = row >> 1;
            const int lr  = (32 * p + lane) >> 1;
            const float* src = (lane & 1) ? (Q1 + lr * QP) : (Q0 + lr * QP);
            const int coff = (lane & 1) ? (-1 - r) : (-r);
            #pragma unroll
            for (int ui = 0; ui < 8; ++ui) {
                const int u = (wrp << 3) + ui;
                const int j = (base128 - u + 32 * p + lane) & 255;
                og[u * 256 + j] = src[(j + coff) & 255];
            }
        }
    }

    CLUSTER_SYNC();     // smem must outlive peer's phase-2 reads
}

// ---------------------------------------------------------------------------

extern "C" void kernel_launch(void* const* d_in, const int* in_sizes, int n_in,
                              void* d_out, int out_size)
{
    const float* y0 = (const float*)d_in[0];
    const float* y1 = (const float*)d_in[1];
    const float* y2 = (const float*)d_in[2];
    const float* y3 = (const float*)d_in[3];

    static bool once = []() {
        cudaFuncSetAttribute(stageA_kernel,
                             cudaFuncAttributeMaxDynamicSharedMemorySize,
                             3 * 128 * P1 * 4);
        cudaFuncSetAttribute(stageB_fused,
                             cudaFuncAttributeMaxDynamicSharedMemorySize,
                             SMB_BYTES);
        return true;
    }();
    (void)once;

    stageA_kernel<<<512, 512, 3 * 128 * P1 * 4>>>(y0, y1, y2, y3);
    stageB_fused<<<512, 1024, SMB_BYTES>>>((float*)d_out);
}